// round 16
// baseline (speedup 1.0000x reference)
#include <cuda_runtime.h>
#include <cuda_fp16.h>
#include <math.h>
#include <stdint.h>

#define NVOX 40000
#define NQ   8192
#define KK   96
#define C    128
#define FF   256
#define NH   8
#define PSS  100

// weight buffer offsets (halfs)
#define W_INW  0
#define W_OUTW 49152
#define W_L1W  65536
#define W_L2W  98304
#define W_FINW 131072
#define W_TOT  147456

// prep kernel block ranges
#define PB_W   576
#define PB_KF  5000
#define PB_QF  4096
#define PB_TOT (PB_W + PB_KF + PB_QF)

// ---------------- scratch (device globals; no allocation) ----------------
__device__ __half g_w[W_TOT];
__device__ __half g_kf[NVOX * C];
__device__ __half g_KVh[NVOX * 2 * C];
__device__ __half g_qf[NQ * C];
__device__ __half g_q16[NQ * C];
__device__ __half g_ctx[NQ * C];
__device__ float  g_att[NQ * C];
__device__ __half g_hn[NQ * C];
__device__ __half g_a1[NQ * FF];
__device__ __half g_x[NQ * C];

// ---------------- helpers ----------------
__device__ __forceinline__ int skey(int r) { return (r ^ (r >> 2)) & 3; }

__device__ __forceinline__ void ldsm4(uint32_t* r, uint32_t addr) {
    asm volatile("ldmatrix.sync.aligned.m8n8.x4.shared.b16 {%0,%1,%2,%3}, [%4];"
                 : "=r"(r[0]), "=r"(r[1]), "=r"(r[2]), "=r"(r[3]) : "r"(addr));
}

__device__ __forceinline__ void mma16(float* d, const uint32_t* a, const uint32_t* b) {
    asm volatile(
        "mma.sync.aligned.m16n8k16.row.col.f32.f16.f16.f32 "
        "{%0,%1,%2,%3}, {%4,%5,%6,%7}, {%8,%9}, {%0,%1,%2,%3};"
        : "+f"(d[0]), "+f"(d[1]), "+f"(d[2]), "+f"(d[3])
        : "r"(a[0]), "r"(a[1]), "r"(a[2]), "r"(a[3]), "r"(b[0]), "r"(b[1]));
}

__device__ __forceinline__ void cpa16(uint32_t s, const void* g) {
    asm volatile("cp.async.cg.shared.global [%0], [%1], 16;" :: "r"(s), "l"(g));
}
__device__ __forceinline__ void cpa_commit() {
    asm volatile("cp.async.commit_group;");
}
template <int N>
__device__ __forceinline__ void cpa_wait() {
    asm volatile("cp.async.wait_group %0;" :: "n"(N));
}

// ---------------- fused prep: weight fp16 + kf (LN+pos) + qfeat -----------
__global__ __launch_bounds__(256)
void prep_kernel(const float* __restrict__ s0, const float* __restrict__ s1,
                 const float* __restrict__ s2, const float* __restrict__ s3,
                 const float* __restrict__ s4,
                 const float* __restrict__ vf, const float* __restrict__ vc,
                 const float* __restrict__ g1, const float* __restrict__ b1,
                 const float* __restrict__ kpw, const float* __restrict__ kpb,
                 const float* __restrict__ qc, const float* __restrict__ qpw,
                 const float* __restrict__ qpb)
{
    const int b = blockIdx.x;
    if (b < PB_W) {
        int i = b * 256 + threadIdx.x;
        const float* s; int off;
        if      (i < W_OUTW) { s = s0; off = W_INW;  }
        else if (i < W_L1W)  { s = s1; off = W_OUTW; }
        else if (i < W_L2W)  { s = s2; off = W_L1W;  }
        else if (i < W_FINW) { s = s3; off = W_L2W;  }
        else                 { s = s4; off = W_FINW; }
        g_w[i] = __float2half(s[i - off]);
    } else if (b < PB_W + PB_KF) {
        int v    = (b - PB_W) * 8 + (threadIdx.x >> 5);
        int lane = threadIdx.x & 31;
        if (v >= NVOX) return;

        float4 x = ((const float4*)(vf + (size_t)v * C))[lane];
        float s = x.x + x.y + x.z + x.w;
        float q = x.x * x.x + x.y * x.y + x.z * x.z + x.w * x.w;
#pragma unroll
        for (int o = 16; o; o >>= 1) {
            s += __shfl_xor_sync(0xffffffffu, s, o);
            q += __shfl_xor_sync(0xffffffffu, q, o);
        }
        float m   = s * (1.0f / 128.0f);
        float var = q * (1.0f / 128.0f) - m * m;
        float r   = rsqrtf(var + 1e-5f);

        float cx = vc[v * 3 + 0], cy = vc[v * 3 + 1], cz = vc[v * 3 + 2];

        const float* xv = &x.x;
#pragma unroll
        for (int j = 0; j < 4; j++) {
            int c = lane * 4 + j;
            float y  = (xv[j] - m) * r * g1[c] + b1[c];
            float kp = fmaxf(kpw[c * 3 + 0] * cx + kpw[c * 3 + 1] * cy +
                             kpw[c * 3 + 2] * cz + kpb[c], 0.0f);
            g_kf[v * C + c] = __float2half(y + kp);
        }
    } else {
        int t = (b - PB_W - PB_KF) * 256 + threadIdx.x;
        int n = t >> 7, c = t & 127;
        float x = qc[n * 3 + 0], y = qc[n * 3 + 1], z = qc[n * 3 + 2];
        float v = fmaxf(qpw[c * 3 + 0] * x + qpw[c * 3 + 1] * y +
                        qpw[c * 3 + 2] * z + qpb[c], 0.0f);
        g_qf[t] = __float2half(v);
    }
}

// ---------------- row LayerNorm (norm2) -> fp16 ----------------
__global__ void ln_kernel(const float* __restrict__ in,
                          const float* __restrict__ g,
                          const float* __restrict__ b)
{
    int r    = blockIdx.x * 8 + (threadIdx.x >> 5);
    int lane = threadIdx.x & 31;

    float4 x = ((const float4*)(in + (size_t)r * C))[lane];
    float s = x.x + x.y + x.z + x.w;
    float q = x.x * x.x + x.y * x.y + x.z * x.z + x.w * x.w;
#pragma unroll
    for (int o = 16; o; o >>= 1) {
        s += __shfl_xor_sync(0xffffffffu, s, o);
        q += __shfl_xor_sync(0xffffffffu, q, o);
    }
    float m   = s * (1.0f / 128.0f);
    float var = q * (1.0f / 128.0f) - m * m;
    float rs  = rsqrtf(var + 1e-5f);

    const float* xv = &x.x;
#pragma unroll
    for (int j = 0; j < 4; j++) {
        int c = lane * 4 + j;
        g_hn[r * C + c] = __float2half((xv[j] - m) * rs * g[c] + b[c]);
    }
}

// ---------------- KV GEMM: 256 threads, CTA 128x128, fp16 single-pass -------
__global__ __launch_bounds__(256, 2)
void mma_kv(const __half* __restrict__ A, const __half* __restrict__ W,
            const float* __restrict__ bias, __half* __restrict__ outh,
            int M, int N, int Kd)
{
    __shared__ __align__(16) __half sA[2][128 * 32];
    __shared__ __align__(16) __half sB[2][128 * 32];

    const int tid  = threadIdx.x;
    const int m0   = blockIdx.x * 128;
    const int n0   = blockIdx.y * 128;
    const int lane = tid & 31;
    const int g    = lane >> 2;
    const int tig  = lane & 3;
    const int warp = tid >> 5;
    const int wm   = warp >> 1;
    const int wn   = warp & 1;

    const int lr = tid >> 2, lc = tid & 3;
    int so[2];
    bool okA[2];
#pragma unroll
    for (int i = 0; i < 2; i++) {
        int r = lr + 64 * i;
        so[i]  = (r * 32 + ((lc ^ skey(r)) << 3)) * 2;
        okA[i] = (m0 + r) < M;
    }

    uint32_t bA[2], bB[2];
#pragma unroll
    for (int bu = 0; bu < 2; bu++) {
        bA[bu] = (uint32_t)__cvta_generic_to_shared(sA[bu]);
        bB[bu] = (uint32_t)__cvta_generic_to_shared(sB[bu]);
    }

    const int mat = lane >> 3, l8 = lane & 7;
    int offA[2][2], offB[4][2];
#pragma unroll
    for (int kh = 0; kh < 2; kh++) {
#pragma unroll
        for (int i = 0; i < 2; i++) {
            int ra = wm * 32 + i * 16 + (mat & 1) * 8 + l8;
            int ca = kh * 2 + (mat >> 1);
            offA[i][kh] = (ra * 32 + ((ca ^ skey(ra)) << 3)) * 2;
        }
#pragma unroll
        for (int i = 0; i < 4; i++) {
            int rb = wn * 64 + i * 16 + (mat >> 1) * 8 + l8;
            int cb = kh * 2 + (mat & 1);
            offB[i][kh] = (rb * 32 + ((cb ^ skey(rb)) << 3)) * 2;
        }
    }

    float acc[2][8][4];
#pragma unroll
    for (int t = 0; t < 2; t++)
#pragma unroll
        for (int j = 0; j < 8; j++)
#pragma unroll
            for (int e = 0; e < 4; e++) acc[t][j][e] = 0.0f;

#pragma unroll
    for (int i = 0; i < 2; i++) {
        if (okA[i]) cpa16(bA[0] + so[i], A + (size_t)(m0 + lr + 64 * i) * Kd + lc * 8);
        cpa16(bB[0] + so[i], W + (size_t)(n0 + lr + 64 * i) * Kd + lc * 8);
    }
    cpa_commit();

    int buf = 0;
    for (int kc = 0; kc < Kd; kc += 32) {
        const bool more = (kc + 32) < Kd;
        if (more) {
            int nb = buf ^ 1;
            int ko = kc + 32;
#pragma unroll
            for (int i = 0; i < 2; i++) {
                if (okA[i]) cpa16(bA[nb] + so[i], A + (size_t)(m0 + lr + 64 * i) * Kd + ko + lc * 8);
                cpa16(bB[nb] + so[i], W + (size_t)(n0 + lr + 64 * i) * Kd + ko + lc * 8);
            }
            cpa_commit();
            cpa_wait<1>();
        } else {
            cpa_wait<0>();
        }
        __syncthreads();

#pragma unroll
        for (int kh = 0; kh < 2; kh++) {
            uint32_t ah[2][4], bh[4][4];
#pragma unroll
            for (int i = 0; i < 2; i++) ldsm4(ah[i], bA[buf] + offA[i][kh]);
#pragma unroll
            for (int i = 0; i < 4; i++) ldsm4(bh[i], bB[buf] + offB[i][kh]);
#pragma unroll
            for (int t = 0; t < 2; t++)
#pragma unroll
                for (int j = 0; j < 8; j++)
                    mma16(acc[t][j], ah[t], &bh[j >> 1][(j & 1) * 2]);
        }
        __syncthreads();
        buf ^= 1;
    }

#pragma unroll
    for (int t = 0; t < 2; t++) {
#pragma unroll
        for (int j = 0; j < 8; j++) {
            int row0 = m0 + wm * 32 + t * 16 + g;
            int col  = n0 + wn * 64 + j * 8 + 2 * tig;
            float2 bi = *(const float2*)(bias + col);
#pragma unroll
            for (int h2 = 0; h2 < 2; h2++) {
                int row = row0 + h2 * 8;
                if (row >= M) continue;
                float x0 = acc[t][j][h2 * 2 + 0] + bi.x;
                float x1 = acc[t][j][h2 * 2 + 1] + bi.y;
                *(__half2*)(outh + (size_t)row * N + col) = __floats2half2_rn(x0, x1);
            }
        }
    }
}

// ---------------- tensor-core GEMM (single-pass fp16) ----------------------
__global__ __launch_bounds__(128)
void mma_gemm(const __half* __restrict__ A, const __half* __restrict__ W,
              const float* __restrict__ bias, const float* __restrict__ res,
              float* __restrict__ out32, __half* __restrict__ outh,
              int N, int Kd, int flags)
{
    __shared__ __align__(16) __half sA[2][64 * 32];
    __shared__ __align__(16) __half sB[2][64 * 32];

    const int tid  = threadIdx.x;
    const int m0   = blockIdx.x * 64;
    const int n0   = blockIdx.y * 64;
    const int lane = tid & 31;
    const int g    = lane >> 2;
    const int tig  = lane & 3;
    const int wm   = tid >> 6;
    const int wn   = (tid >> 5) & 1;

    const int lr0 = tid >> 2, lc = tid & 3, lr1 = lr0 + 32;
    const int so0 = (lr0 * 32 + ((lc ^ skey(lr0)) << 3)) * 2;
    const int so1 = (lr1 * 32 + ((lc ^ skey(lr1)) << 3)) * 2;

    uint32_t bA[2], bB[2];
#pragma unroll
    for (int bu = 0; bu < 2; bu++) {
        bA[bu] = (uint32_t)__cvta_generic_to_shared(sA[bu]);
        bB[bu] = (uint32_t)__cvta_generic_to_shared(sB[bu]);
    }

    const int mat = lane >> 3, l8 = lane & 7;
    int offA[2][2], offB[2][2];
#pragma unroll
    for (int i = 0; i < 2; i++)
#pragma unroll
        for (int kh = 0; kh < 2; kh++) {
            int ra = wm * 32 + i * 16 + (mat & 1) * 8 + l8;
            int ca = kh * 2 + (mat >> 1);
            offA[i][kh] = (ra * 32 + ((ca ^ skey(ra)) << 3)) * 2;
            int rb = wn * 32 + i * 16 + (mat >> 1) * 8 + l8;
            int cb = kh * 2 + (mat & 1);
            offB[i][kh] = (rb * 32 + ((cb ^ skey(rb)) << 3)) * 2;
        }

    float acc[2][4][4];
#pragma unroll
    for (int t = 0; t < 2; t++)
#pragma unroll
        for (int j = 0; j < 4; j++)
#pragma unroll
            for (int e = 0; e < 4; e++) acc[t][j][e] = 0.0f;

    cpa16(bA[0] + so0, A + (size_t)(m0 + lr0) * Kd + lc * 8);
    cpa16(bA[0] + so1, A + (size_t)(m0 + lr1) * Kd + lc * 8);
    cpa16(bB[0] + so0, W + (size_t)(n0 + lr0) * Kd + lc * 8);
    cpa16(bB[0] + so1, W + (size_t)(n0 + lr1) * Kd + lc * 8);
    cpa_commit();

    int buf = 0;
    for (int kc = 0; kc < Kd; kc += 32) {
        const bool more = (kc + 32) < Kd;
        if (more) {
            int nb = buf ^ 1;
            int ko = kc + 32;
            cpa16(bA[nb] + so0, A + (size_t)(m0 + lr0) * Kd + ko + lc * 8);
            cpa16(bA[nb] + so1, A + (size_t)(m0 + lr1) * Kd + ko + lc * 8);
            cpa16(bB[nb] + so0, W + (size_t)(n0 + lr0) * Kd + ko + lc * 8);
            cpa16(bB[nb] + so1, W + (size_t)(n0 + lr1) * Kd + ko + lc * 8);
            cpa_commit();
            cpa_wait<1>();
        } else {
            cpa_wait<0>();
        }
        __syncthreads();

#pragma unroll
        for (int kh = 0; kh < 2; kh++) {
            uint32_t ah[2][4], bh[2][4];
#pragma unroll
            for (int i = 0; i < 2; i++) {
                ldsm4(ah[i], bA[buf] + offA[i][kh]);
                ldsm4(bh[i], bB[buf] + offB[i][kh]);
            }
#pragma unroll
            for (int t = 0; t < 2; t++)
#pragma unroll
                for (int j = 0; j < 4; j++)
                    mma16(acc[t][j], ah[t], &bh[j >> 1][(j & 1) * 2]);
        }
        __syncthreads();
        buf ^= 1;
    }

#pragma unroll
    for (int t = 0; t < 2; t++) {
#pragma unroll
        for (int j = 0; j < 4; j++) {
            int row0 = m0 + wm * 32 + t * 16 + g;
            int col  = n0 + wn * 32 + j * 8 + 2 * tig;
            float2 bi = *(const float2*)(bias + col);
#pragma unroll
            for (int h2 = 0; h2 < 2; h2++) {
                int row = row0 + h2 * 8;
                float x0 = acc[t][j][h2 * 2 + 0] + bi.x;
                float x1 = acc[t][j][h2 * 2 + 1] + bi.y;
                size_t o = (size_t)row * N + col;
                if (flags & 2) {
                    float2 r2 = *(const float2*)(res + o);
                    x0 += r2.x; x1 += r2.y;
                }
                if (flags & 1) { x0 = fmaxf(x0, 0.0f); x1 = fmaxf(x1, 0.0f); }
                if (flags & 8)  *(float2*)(out32 + o) = make_float2(x0, x1);
                if (flags & 4)  *(__half2*)(outh + o) = __floats2half2_rn(x0, x1);
            }
        }
    }
}

// ---------------- attention: one block per query, 128 threads ----------------
// Branchless register-direct gather; q pre-scaled by 1/sqrt(DH) (exact pow2).
__global__ __launch_bounds__(128)
void attn_kernel(const int* __restrict__ kidx)
{
    __shared__ int   idx_s[KK];
    __shared__ float p_s[NH][PSS];
    __shared__ __align__(16) float red_s[4][C];

    const int n  = blockIdx.x;
    const int t  = threadIdx.x;
    const int rg = t >> 4;     // key subgroup
    const int pp = t & 15;     // 8-channel block
    const int hh = pp >> 1;    // head owning channels pp*8..pp*8+7

    if (t < KK) idx_s[t] = kidx[n * KK + t];

    // q channels pp*8..pp*8+7, pre-scaled by 0.25 (exact power of two)
    __half2 q2[4];
    {
        uint4 qv = *(const uint4*)(g_q16 + (size_t)n * C + pp * 8);
        const __half2* qh = (const __half2*)&qv;
        const __half2 s2 = __float2half2_rn(0.25f);
        q2[0] = __hmul2(qh[0], s2);
        q2[1] = __hmul2(qh[1], s2);
        q2[2] = __hmul2(qh[2], s2);
        q2[3] = __hmul2(qh[3], s2);
    }
    __syncthreads();

    // ---- scores (branchless fp16 dot): key k = i*8+rg; pair-sum (pp,pp^1) ----
#pragma unroll
    for (int i = 0; i < 12; i++) {
        int k = i * 8 + rg;
        int v = idx_s[k];
        v = v < 0 ? 0 : v;                               // clamp; masked later
        uint4 k4 = *(const uint4*)(g_KVh + (size_t)v * 256 + pp * 8);
        const __half2* kh = (const __half2*)&k4;
        __half2 a2 = __hmul2(q2[0], kh[0]);
        a2 = __hfma2(q2[1], kh[1], a2);
        a2 = __hfma2(q2[2], kh[2], a2);
        a2 = __hfma2(q2[3], kh[3], a2);
        float partial = __low2float(a2) + __high2float(a2);
        partial += __shfl_xor_sync(0xffffffffu, partial, 1);
        if ((pp & 1) == 0) p_s[hh][k] = partial;
    }
    __syncthreads();

    // ---- softmax per head: thread (h=rg, l16=pp) handles k = l16+16m ----
    {
        const int h = rg, l16 = pp;
        float sc[6]; int vm[6];
#pragma unroll
        for (int m = 0; m < 6; m++) {
            int k = l16 + m * 16;
            vm[m] = idx_s[k];
            sc[m] = p_s[h][k];
        }
        float mx = -1e30f;
#pragma unroll
        for (int m = 0; m < 6; m++)
            if (vm[m] >= 0) mx = fmaxf(mx, sc[m]);
#pragma unroll
        for (int o = 8; o; o >>= 1)
            mx = fmaxf(mx, __shfl_xor_sync(0xffffffffu, mx, o, 16));

        float p[6];
        float sum = 0.0f;
#pragma unroll
        for (int m = 0; m < 6; m++) {
            p[m] = (vm[m] >= 0) ? __expf(sc[m] - mx) : 0.0f;
            sum += p[m];
        }
#pragma unroll
        for (int o = 8; o; o >>= 1)
            sum += __shfl_xor_sync(0xffffffffu, sum, o, 16);
        const float inv = 1.0f / sum;
#pragma unroll
        for (int m = 0; m < 6; m++) p_s[h][l16 + m * 16] = p[m] * inv;
    }
    __syncthreads();

    // ---- ctx: branchless register accumulation (fp32); p=0 kills masked ----
    float facc[8];
#pragma unroll
    for (int j = 0; j < 8; j++) facc[j] = 0.0f;
#pragma unroll
    for (int i = 0; i < 12; i++) {
        int k = i * 8 + rg;
        int v = idx_s[k];
        v = v < 0 ? 0 : v;
        float pk = p_s[hh][k];
        uint4 v4 = *(const uint4*)(g_KVh + (size_t)v * 256 + 128 + pp * 8);
        const __half2* vh = (const __half2*)&v4;
#pragma unroll
        for (int j = 0; j < 4; j++) {
            float2 f = __half22float2(vh[j]);
            facc[2 * j + 0] += pk * f.x;
            facc[2 * j + 1] += pk * f.y;
        }
    }
#pragma unroll
    for (int j = 0; j < 8; j++)
        facc[j] += __shfl_xor_sync(0xffffffffu, facc[j], 16);
    const int w = t >> 5;
    if ((t & 16) == 0) {
        *(float4*)&red_s[w][pp * 8]     = make_float4(facc[0], facc[1], facc[2], facc[3]);
        *(float4*)&red_s[w][pp * 8 + 4] = make_float4(facc[4], facc[5], facc[6], facc[7]);
    }
    __syncthreads();

    float acc = red_s[0][t] + red_s[1][t] + red_s[2][t] + red_s[3][t];
    g_ctx[n * C + t] = __float2half(acc);
}

// ---------------- host launch ----------------
extern "C" void kernel_launch(void* const* d_in, const int* in_sizes, int n_in,
                              void* d_out, int out_size)
{
    const float* vf   = (const float*)d_in[0];
    const float* vc   = (const float*)d_in[1];
    const float* qc   = (const float*)d_in[2];
    const int*   kidx = (const int*)  d_in[3];
    const float* n1g  = (const float*)d_in[4];
    const float* n1b  = (const float*)d_in[5];
    const float* qpw  = (const float*)d_in[6];
    const float* qpb  = (const float*)d_in[7];
    const float* kpw  = (const float*)d_in[8];
    const float* kpb  = (const float*)d_in[9];
    const float* inw  = (const float*)d_in[10];
    const float* inb  = (const float*)d_in[11];
    const float* outw = (const float*)d_in[12];
    const float* outb = (const float*)d_in[13];
    const float* n2g  = (const float*)d_in[14];
    const float* n2b  = (const float*)d_in[15];
    const float* l1w  = (const float*)d_in[16];
    const float* l1b  = (const float*)d_in[17];
    const float* l2w  = (const float*)d_in[18];
    const float* l2b  = (const float*)d_in[19];
    const float* fw   = (const float*)d_in[20];
    const float* fb   = (const float*)d_in[21];
    float* out = (float*)d_out;

    __half *p_kf, *p_qf, *p_q16, *p_ctx, *p_hn, *p_a1, *p_x, *p_w, *p_KVh;
    float *p_att;
    cudaGetSymbolAddress((void**)&p_kf,  g_kf);
    cudaGetSymbolAddress((void**)&p_KVh, g_KVh);
    cudaGetSymbolAddress((void**)&p_qf,  g_qf);
    cudaGetSymbolAddress((void**)&p_q16, g_q16);
    cudaGetSymbolAddress((void**)&p_ctx, g_ctx);
    cudaGetSymbolAddress((void**)&p_att, g_att);
    cudaGetSymbolAddress((void**)&p_hn,  g_hn);
    cudaGetSymbolAddress((void**)&p_a1,  g_a1);
    cudaGetSymbolAddress((void**)&p_x,   g_x);
    cudaGetSymbolAddress((void**)&p_w,   g_w);

    // 0) fused prep: weight fp16 + kf + qfeat
    prep_kernel<<<PB_TOT, 256>>>(inw, outw, l1w, l2w, fw,
                                 vf, vc, n1g, n1b, kpw, kpb,
                                 qc, qpw, qpb);

    // 1) per-voxel K|V projection -> fp16 [NVOX,256]
    mma_kv<<<dim3((NVOX + 127) / 128, 2), 256>>>(
        p_kf, p_w + W_INW + 128 * 128, inb + 128, p_KVh, NVOX, 256, 128);

    // 2) q projection -> fp16
    mma_gemm<<<dim3(NQ / 64, 2), 128>>>(
        p_qf, p_w + W_INW, inb, nullptr, nullptr, p_q16, 128, 128, 4);

    // 3) sparse attention -> ctx fp16
    attn_kernel<<<NQ, 128>>>(kidx);

    // 4) output projection -> attend fp32
    mma_gemm<<<dim3(NQ / 64, 2), 128>>>(
        p_ctx, p_w + W_OUTW, outb, nullptr, p_att, nullptr, 128, 128, 8);

    // 5) norm2 -> hn fp16
    ln_kernel<<<NQ / 8, 256>>>(p_att, n2g, n2b);

    // 6) FFN up (relu) -> a1 fp16
    mma_gemm<<<dim3(NQ / 64, 4), 128>>>(
        p_hn, p_w + W_L1W, l1b, nullptr, nullptr, p_a1, 256, 128, 4 | 1);

    // 7) FFN down + residual(attend) -> x fp16
    mma_gemm<<<dim3(NQ / 64, 2), 128>>>(
        p_a1, p_w + W_L2W, l2b, p_att, nullptr, p_x, 128, 256, 4 | 2);

    // 8) final projection + relu -> output fp32
    mma_gemm<<<dim3(NQ / 64, 2), 128>>>(
        p_x, p_w + W_FINW, fb, nullptr, out, nullptr, 128, 128, 8 | 1);
}